// round 3
// baseline (speedup 1.0000x reference)
#include <cuda_runtime.h>
#include <cuda_bf16.h>
#include <cstdint>

#define BATCH 8
#define SEQ 512
#define DM 512
#define NELEM (BATCH*SEQ*DM)

// ============================ scratch (bf16 hi/lo splits) ============================
__device__ __align__(16) __nv_bfloat16 g_Qhi[NELEM];
__device__ __align__(16) __nv_bfloat16 g_Qlo[NELEM];
__device__ __align__(16) __nv_bfloat16 g_QRhi[NELEM];
__device__ __align__(16) __nv_bfloat16 g_QRlo[NELEM];
__device__ __align__(16) __nv_bfloat16 g_Khi[NELEM];
__device__ __align__(16) __nv_bfloat16 g_Klo[NELEM];
__device__ __align__(16) __nv_bfloat16 g_Ethi[DM*DM];
__device__ __align__(16) __nv_bfloat16 g_Etlo[DM*DM];

__device__ __forceinline__ void split_bf16(float x, __nv_bfloat16& h, __nv_bfloat16& l) {
    h = __float2bfloat16(x);
    l = __float2bfloat16(x - __bfloat162float(h));
}

__device__ __forceinline__ uint32_t smem_u32(const void* p) {
    uint32_t a;
    asm("{ .reg .u64 t; cvta.to.shared.u64 t, %1; cvt.u32.u64 %0, t; }" : "=r"(a) : "l"(p));
    return a;
}

// ============================ prep kernels ============================
// One block per (b, i) row: split Q and build+split Qrev.
// Qrev[b,i,0] = sum_{j>=i} q[b,i,j]; Qrev[b,i,d] = q[b,i,i-d] for 1<=d<=i; else 0.
__global__ void prep_q_kernel(const float* __restrict__ q) {
    int bid = blockIdx.x;            // b*SEQ + i
    int i = bid & (SEQ - 1);
    int t = threadIdx.x;             // 128 threads
    __shared__ float row[DM];
    __shared__ float red[128];

    const float4* src = reinterpret_cast<const float4*>(q + (size_t)bid * DM);
    reinterpret_cast<float4*>(row)[t] = src[t];
    __syncthreads();

    float p = 0.f;
    #pragma unroll
    for (int j = t; j < DM; j += 128)
        if (j >= i) p += row[j];
    red[t] = p;
    __syncthreads();
    #pragma unroll
    for (int s = 64; s > 0; s >>= 1) {
        if (t < s) red[t] += red[t + s];
        __syncthreads();
    }
    float suf = red[0];

    size_t base = (size_t)bid * DM;
    #pragma unroll
    for (int d = t; d < DM; d += 128) {
        float x = row[d];
        split_bf16(x, g_Qhi[base + d], g_Qlo[base + d]);
        float r = (d == 0) ? suf : ((d <= i) ? row[i - d] : 0.f);
        split_bf16(r, g_QRhi[base + d], g_QRlo[base + d]);
    }
}

__global__ void prep_k_kernel(const float* __restrict__ k) {
    int idx = blockIdx.x * blockDim.x + threadIdx.x;
    int stride = gridDim.x * blockDim.x;
    for (int j = idx; j < NELEM; j += stride)
        split_bf16(k[j], g_Khi[j], g_Klo[j]);
}

// Transposed split of E: Et[n, d] = E[d, n]
__global__ void prep_e_kernel(const float* __restrict__ e) {
    __shared__ float tile[32][33];
    int bx = blockIdx.x, by = blockIdx.y;
    int tx = threadIdx.x, ty = threadIdx.y;   // 32 x 8
    int x = bx * 32 + tx;
    #pragma unroll
    for (int j = ty; j < 32; j += 8)
        tile[j][tx] = e[(size_t)(by * 32 + j) * DM + x];
    __syncthreads();
    #pragma unroll
    for (int j = ty; j < 32; j += 8) {
        size_t o = (size_t)(bx * 32 + j) * DM + by * 32 + tx;
        split_bf16(tile[tx][j], g_Ethi[o], g_Etlo[o]);
    }
}

// ============================ main GEMM (mma.sync bf16) ============================
// out[b,i,n] = Q[b,i,:].K[b,n,:] + Qrev[b,i,:].Et[n,:]
// 6 K-segments of 512 each: {Qhi,Khi} {Qlo,Khi} {Qhi,Klo} {QRhi,Ethi} {QRlo,Ethi} {QRhi,Etlo}

#define BM 128
#define BN 128
#define BK 64                               // bf16 per chunk (128 B rows -> 8x16B)
#define TILE_B (BM * BK * 2)                // 16384 bytes per operand tile
#define BUF_B  (2 * TILE_B)                 // A + B per stage
#define SMEM_TOTAL (2 * BUF_B)              // double buffered = 65536
#define NCHUNK 48                           // 6 segments * (512/64)

// swizzled smem byte offset for (row, bf16-col kk) in a 128x64 bf16 tile
__device__ __forceinline__ uint32_t sw_off(int row, int kk) {
    return (uint32_t)(row * 128 + (((kk >> 3) ^ (row & 7)) << 4) + ((kk & 7) << 1));
}

__device__ __forceinline__ void cp_async16(uint32_t saddr, const void* gaddr) {
    asm volatile("cp.async.cg.shared.global [%0], [%1], 16;" :: "r"(saddr), "l"(gaddr));
}

__device__ __forceinline__ void ldmatrix_x4(uint32_t& r0, uint32_t& r1, uint32_t& r2,
                                            uint32_t& r3, uint32_t addr) {
    asm volatile("ldmatrix.sync.aligned.m8n8.x4.shared.b16 {%0,%1,%2,%3}, [%4];"
                 : "=r"(r0), "=r"(r1), "=r"(r2), "=r"(r3) : "r"(addr));
}

__device__ __forceinline__ void mma16816(float* c, const uint32_t* a, uint32_t b0, uint32_t b1) {
    asm volatile(
        "mma.sync.aligned.m16n8k16.row.col.f32.bf16.bf16.f32 "
        "{%0,%1,%2,%3}, {%4,%5,%6,%7}, {%8,%9}, {%0,%1,%2,%3};"
        : "+f"(c[0]), "+f"(c[1]), "+f"(c[2]), "+f"(c[3])
        : "r"(a[0]), "r"(a[1]), "r"(a[2]), "r"(a[3]), "r"(b0), "r"(b1));
}

__global__ __launch_bounds__(256, 1) void rel_gemm_kernel(float* __restrict__ out) {
    extern __shared__ char smem[];
    uint32_t sb = smem_u32(smem);

    int tid = threadIdx.x;
    int lane = tid & 31, wid = tid >> 5;
    int wm = wid & 3, wn = wid >> 2;          // 4 m-warps x 2 n-warps
    int n0 = blockIdx.x * BN;
    int m0 = blockIdx.y * BM;
    int b  = blockIdx.z;
    size_t boff = (size_t)b * SEQ * DM;

    const __nv_bfloat16* Asrc[6] = { g_Qhi + boff, g_Qlo + boff, g_Qhi + boff,
                                     g_QRhi + boff, g_QRlo + boff, g_QRhi + boff };
    const __nv_bfloat16* Bsrc[6] = { g_Khi + boff, g_Khi + boff, g_Klo + boff,
                                     g_Ethi, g_Ethi, g_Etlo };

    float acc[2][8][4];
    #pragma unroll
    for (int mi = 0; mi < 2; mi++)
        #pragma unroll
        for (int ni = 0; ni < 8; ni++)
            #pragma unroll
            for (int j = 0; j < 4; j++) acc[mi][ni][j] = 0.f;

    // stage loader: copy chunk `it` into buffer `buf`
    auto load_chunk = [&](int it, int buf) {
        int seg = it / 8, kc = it & 7;
        const __nv_bfloat16* Ag = Asrc[seg] + (size_t)m0 * DM + kc * BK;
        const __nv_bfloat16* Bg = Bsrc[seg] + (size_t)n0 * DM + kc * BK;
        uint32_t a_s = sb + buf * BUF_B;
        uint32_t b_s = a_s + TILE_B;
        #pragma unroll
        for (int r2 = 0; r2 < 4; r2++) {
            int idx = tid + r2 * 256;          // 0..1023
            int row = idx >> 3, ck = idx & 7;  // 128 rows x 8 16B-chunks
            uint32_t so = (uint32_t)(row * 128 + ((ck ^ (row & 7)) << 4));
            cp_async16(a_s + so, Ag + row * DM + ck * 8);
            cp_async16(b_s + so, Bg + row * DM + ck * 8);
        }
        asm volatile("cp.async.commit_group;");
    };

    load_chunk(0, 0);

    for (int it = 0; it < NCHUNK; it++) {
        if (it + 1 < NCHUNK) {
            load_chunk(it + 1, (it + 1) & 1);
            asm volatile("cp.async.wait_group 1;");
        } else {
            asm volatile("cp.async.wait_group 0;");
        }
        __syncthreads();

        uint32_t a_s = sb + (it & 1) * BUF_B;
        uint32_t b_s = a_s + TILE_B;

        #pragma unroll
        for (int k16 = 0; k16 < 4; k16++) {
            int kc = k16 * 16;
            // A frags: 2 x (m16 x k16) via ldmatrix.x4
            uint32_t af[2][4];
            #pragma unroll
            for (int mi = 0; mi < 2; mi++) {
                int row = wm * 32 + mi * 16 + (lane & 7) + ((lane >> 3) & 1) * 8;
                int kk  = kc + ((lane >> 4) << 3);
                ldmatrix_x4(af[mi][0], af[mi][1], af[mi][2], af[mi][3],
                            a_s + sw_off(row, kk));
            }
            // B frags: 4 x (n16 x k16) via ldmatrix.x4 -> two n8 frags each
            uint32_t bf[4][4];
            #pragma unroll
            for (int nb = 0; nb < 4; nb++) {
                int row = wn * 64 + nb * 16 + (lane & 7) + ((lane >> 4) << 3);
                int kk  = kc + (((lane >> 3) & 1) << 3);
                ldmatrix_x4(bf[nb][0], bf[nb][1], bf[nb][2], bf[nb][3],
                            b_s + sw_off(row, kk));
            }
            #pragma unroll
            for (int mi = 0; mi < 2; mi++)
                #pragma unroll
                for (int nb = 0; nb < 4; nb++) {
                    mma16816(acc[mi][nb * 2 + 0], af[mi], bf[nb][0], bf[nb][1]);
                    mma16816(acc[mi][nb * 2 + 1], af[mi], bf[nb][2], bf[nb][3]);
                }
        }
        __syncthreads();
    }

    // epilogue: accum regs -> gmem
    int qr = lane >> 2, qc = (lane & 3) << 1;
    #pragma unroll
    for (int mi = 0; mi < 2; mi++) {
        int r0 = m0 + wm * 32 + mi * 16 + qr;
        #pragma unroll
        for (int ni = 0; ni < 8; ni++) {
            int c = n0 + wn * 64 + ni * 8 + qc;
            float* o0 = out + ((size_t)b * SEQ + r0) * DM + c;
            float* o1 = o0 + 8 * DM;
            float2 v0 = make_float2(acc[mi][ni][0], acc[mi][ni][1]);
            float2 v1 = make_float2(acc[mi][ni][2], acc[mi][ni][3]);
            *reinterpret_cast<float2*>(o0) = v0;
            *reinterpret_cast<float2*>(o1) = v1;
        }
    }
}

// ============================ launch ============================
extern "C" void kernel_launch(void* const* d_in, const int* in_sizes, int n_in,
                              void* d_out, int out_size) {
    const float* q = (const float*)d_in[0];
    const float* k = (const float*)d_in[1];
    const float* e = (const float*)d_in[2];
    float* out = (float*)d_out;

    cudaFuncSetAttribute(rel_gemm_kernel,
                         cudaFuncAttributeMaxDynamicSharedMemorySize, SMEM_TOTAL);

    prep_q_kernel<<<BATCH * SEQ, 128>>>(q);
    prep_k_kernel<<<2048, 256>>>(k);
    prep_e_kernel<<<dim3(16, 16), dim3(32, 8)>>>(e);
    rel_gemm_kernel<<<dim3(SEQ / BN, SEQ / BM, BATCH), 256, SMEM_TOTAL>>>(out);
}

// round 5
// speedup vs baseline: 1.1750x; 1.1750x over previous
#include <cuda_runtime.h>
#include <cuda_bf16.h>
#include <cstdint>

#define BATCH 8
#define SEQ 512
#define DM 512
#define NELEM (BATCH*SEQ*DM)

// ============================ scratch (bf16 hi/lo splits) ============================
__device__ __align__(16) __nv_bfloat16 g_Qhi[NELEM];
__device__ __align__(16) __nv_bfloat16 g_Qlo[NELEM];
__device__ __align__(16) __nv_bfloat16 g_QRhi[NELEM];
__device__ __align__(16) __nv_bfloat16 g_QRlo[NELEM];
__device__ __align__(16) __nv_bfloat16 g_Khi[NELEM];
__device__ __align__(16) __nv_bfloat16 g_Klo[NELEM];
__device__ __align__(16) __nv_bfloat16 g_Ethi[DM*DM];
__device__ __align__(16) __nv_bfloat16 g_Etlo[DM*DM];

__device__ __forceinline__ void split_bf16(float x, __nv_bfloat16& h, __nv_bfloat16& l) {
    h = __float2bfloat16(x);
    l = __float2bfloat16(x - __bfloat162float(h));
}

__device__ __forceinline__ uint32_t smem_u32(const void* p) {
    uint32_t a;
    asm("{ .reg .u64 t; cvta.to.shared.u64 t, %1; cvt.u32.u64 %0, t; }" : "=r"(a) : "l"(p));
    return a;
}

// ============================ prep kernels ============================
__global__ void prep_q_kernel(const float* __restrict__ q) {
    int bid = blockIdx.x;            // b*SEQ + i
    int i = bid & (SEQ - 1);
    int t = threadIdx.x;             // 128 threads
    __shared__ float row[DM];
    __shared__ float red[128];

    const float4* src = reinterpret_cast<const float4*>(q + (size_t)bid * DM);
    reinterpret_cast<float4*>(row)[t] = src[t];
    __syncthreads();

    float p = 0.f;
    #pragma unroll
    for (int j = t; j < DM; j += 128)
        if (j >= i) p += row[j];
    red[t] = p;
    __syncthreads();
    #pragma unroll
    for (int s = 64; s > 0; s >>= 1) {
        if (t < s) red[t] += red[t + s];
        __syncthreads();
    }
    float suf = red[0];

    size_t base = (size_t)bid * DM;
    #pragma unroll
    for (int d = t; d < DM; d += 128) {
        float x = row[d];
        split_bf16(x, g_Qhi[base + d], g_Qlo[base + d]);
        float r = (d == 0) ? suf : ((d <= i) ? row[i - d] : 0.f);
        split_bf16(r, g_QRhi[base + d], g_QRlo[base + d]);
    }
}

__global__ void prep_k_kernel(const float* __restrict__ k) {
    int idx = blockIdx.x * blockDim.x + threadIdx.x;
    int n4 = NELEM / 4;
    int stride = gridDim.x * blockDim.x;
    for (int j = idx; j < n4; j += stride) {
        float4 v = reinterpret_cast<const float4*>(k)[j];
        __nv_bfloat16 h[4], l[4];
        split_bf16(v.x, h[0], l[0]);
        split_bf16(v.y, h[1], l[1]);
        split_bf16(v.z, h[2], l[2]);
        split_bf16(v.w, h[3], l[3]);
        reinterpret_cast<uint2*>(g_Khi)[j] = *reinterpret_cast<uint2*>(h);
        reinterpret_cast<uint2*>(g_Klo)[j] = *reinterpret_cast<uint2*>(l);
    }
}

// Transposed split of E: Et[n, d] = E[d, n]
__global__ void prep_e_kernel(const float* __restrict__ e) {
    __shared__ float tile[32][33];
    int bx = blockIdx.x, by = blockIdx.y;
    int tx = threadIdx.x, ty = threadIdx.y;   // 32 x 8
    int x = bx * 32 + tx;
    #pragma unroll
    for (int j = ty; j < 32; j += 8)
        tile[j][tx] = e[(size_t)(by * 32 + j) * DM + x];
    __syncthreads();
    #pragma unroll
    for (int j = ty; j < 32; j += 8) {
        size_t o = (size_t)(bx * 32 + j) * DM + by * 32 + tx;
        split_bf16(tile[tx][j], g_Ethi[o], g_Etlo[o]);
    }
}

// ============================ main GEMM (mma.sync bf16, term-shared) ============================
// out[b,i,n] = Qhi.Khi + Qhi.Klo + Qlo.Khi  +  QRhi.Ethi + QRhi.Etlo + QRlo.Ethi
// Stage holds {Ahi, Alo, Bhi, Blo} for one 64-wide K chunk; 3 mma terms per frag set.

#define BM 128
#define BN 64
#define BK 64
#define AT_B (BM * BK * 2)                  // 16384 per A tile
#define BT_B (BN * BK * 2)                  // 8192 per B tile
#define STAGE_B (2 * AT_B + 2 * BT_B)       // 49152
#define SMEM_TOTAL (2 * STAGE_B)            // 98304 (2 stages), 2 CTAs/SM
#define NCHUNK 16                           // 2 passes * 8 chunks of K=64

// offsets within a stage
#define OFF_AH 0
#define OFF_AL AT_B
#define OFF_BH (2 * AT_B)
#define OFF_BL (2 * AT_B + BT_B)

// swizzled smem byte offset for (row, bf16-col kk) in a row-128B tile
__device__ __forceinline__ uint32_t sw_off(int row, int kk) {
    return (uint32_t)(row * 128 + (((kk >> 3) ^ (row & 7)) << 4) + ((kk & 7) << 1));
}

__device__ __forceinline__ void cp_async16(uint32_t saddr, const void* gaddr) {
    asm volatile("cp.async.cg.shared.global [%0], [%1], 16;" :: "r"(saddr), "l"(gaddr));
}

__device__ __forceinline__ void ldmatrix_x4(uint32_t& r0, uint32_t& r1, uint32_t& r2,
                                            uint32_t& r3, uint32_t addr) {
    asm volatile("ldmatrix.sync.aligned.m8n8.x4.shared.b16 {%0,%1,%2,%3}, [%4];"
                 : "=r"(r0), "=r"(r1), "=r"(r2), "=r"(r3) : "r"(addr));
}

__device__ __forceinline__ void mma16816(float* c, const uint32_t* a, uint32_t b0, uint32_t b1) {
    asm volatile(
        "mma.sync.aligned.m16n8k16.row.col.f32.bf16.bf16.f32 "
        "{%0,%1,%2,%3}, {%4,%5,%6,%7}, {%8,%9}, {%0,%1,%2,%3};"
        : "+f"(c[0]), "+f"(c[1]), "+f"(c[2]), "+f"(c[3])
        : "r"(a[0]), "r"(a[1]), "r"(a[2]), "r"(a[3]), "r"(b0), "r"(b1));
}

__global__ __launch_bounds__(256, 2) void rel_gemm_kernel(float* __restrict__ out) {
    extern __shared__ char smem[];
    uint32_t sb = smem_u32(smem);

    int tid = threadIdx.x;
    int lane = tid & 31, wid = tid >> 5;
    int wm = wid & 3, wn = wid >> 2;          // 4 m-warps x 2 n-warps, warp tile 32x32
    int n0 = blockIdx.x * BN;
    int m0 = blockIdx.y * BM;
    int b  = blockIdx.z;
    size_t boff = (size_t)b * SEQ * DM;

    // pass 0: A={Qhi,Qlo}+boff, B={Khi,Klo}+boff ; pass 1: A={QRhi,QRlo}+boff, B={Ethi,Etlo}
    const __nv_bfloat16* AH[2] = { g_Qhi + boff, g_QRhi + boff };
    const __nv_bfloat16* AL[2] = { g_Qlo + boff, g_QRlo + boff };
    const __nv_bfloat16* BH[2] = { g_Khi + boff, g_Ethi };
    const __nv_bfloat16* BL[2] = { g_Klo + boff, g_Etlo };

    float acc[2][4][4];
    #pragma unroll
    for (int mi = 0; mi < 2; mi++)
        #pragma unroll
        for (int ni = 0; ni < 4; ni++)
            #pragma unroll
            for (int j = 0; j < 4; j++) acc[mi][ni][j] = 0.f;

    auto load_chunk = [&](int it, int buf) {
        int pass = it >> 3, kc = it & 7;
        const __nv_bfloat16* ah = AH[pass] + (size_t)m0 * DM + kc * BK;
        const __nv_bfloat16* al = AL[pass] + (size_t)m0 * DM + kc * BK;
        const __nv_bfloat16* bh = BH[pass] + (size_t)n0 * DM + kc * BK;
        const __nv_bfloat16* bl = BL[pass] + (size_t)n0 * DM + kc * BK;
        uint32_t st = sb + buf * STAGE_B;
        #pragma unroll
        for (int r2 = 0; r2 < 4; r2++) {          // A tiles: 128 rows x 8 chunks
            int idx = tid + r2 * 256;
            int row = idx >> 3, ck = idx & 7;
            uint32_t so = (uint32_t)(row * 128 + ((ck ^ (row & 7)) << 4));
            cp_async16(st + OFF_AH + so, ah + row * DM + ck * 8);
            cp_async16(st + OFF_AL + so, al + row * DM + ck * 8);
        }
        #pragma unroll
        for (int r2 = 0; r2 < 2; r2++) {          // B tiles: 64 rows x 8 chunks
            int idx = tid + r2 * 256;
            int row = idx >> 3, ck = idx & 7;
            uint32_t so = (uint32_t)(row * 128 + ((ck ^ (row & 7)) << 4));
            cp_async16(st + OFF_BH + so, bh + row * DM + ck * 8);
            cp_async16(st + OFF_BL + so, bl + row * DM + ck * 8);
        }
        asm volatile("cp.async.commit_group;");
    };

    load_chunk(0, 0);

    for (int it = 0; it < NCHUNK; it++) {
        if (it + 1 < NCHUNK) {
            load_chunk(it + 1, (it + 1) & 1);
            asm volatile("cp.async.wait_group 1;");
        } else {
            asm volatile("cp.async.wait_group 0;");
        }
        __syncthreads();

        uint32_t st = sb + (it & 1) * STAGE_B;

        #pragma unroll
        for (int k16 = 0; k16 < 4; k16++) {
            int kc = k16 * 16;
            // A fragments (hi & lo): 2 x m16 each
            uint32_t ah[2][4], al[2][4];
            #pragma unroll
            for (int mi = 0; mi < 2; mi++) {
                int row = wm * 32 + mi * 16 + (lane & 7) + ((lane >> 3) & 1) * 8;
                int kk  = kc + ((lane >> 4) << 3);
                uint32_t so = sw_off(row, kk);
                ldmatrix_x4(ah[mi][0], ah[mi][1], ah[mi][2], ah[mi][3], st + OFF_AH + so);
                ldmatrix_x4(al[mi][0], al[mi][1], al[mi][2], al[mi][3], st + OFF_AL + so);
            }
            // B fragments (hi & lo): 2 x n16 each -> 4 n8 frags per matrix
            uint32_t bh[2][4], bl[2][4];
            #pragma unroll
            for (int nb = 0; nb < 2; nb++) {
                int row = wn * 32 + nb * 16 + (lane & 7) + ((lane >> 4) << 3);
                int kk  = kc + (((lane >> 3) & 1) << 3);
                uint32_t so = sw_off(row, kk);
                ldmatrix_x4(bh[nb][0], bh[nb][1], bh[nb][2], bh[nb][3], st + OFF_BH + so);
                ldmatrix_x4(bl[nb][0], bl[nb][1], bl[nb][2], bl[nb][3], st + OFF_BL + so);
            }
            // 3 compensation terms into the same accumulators
            #pragma unroll
            for (int mi = 0; mi < 2; mi++)
                #pragma unroll
                for (int nb = 0; nb < 2; nb++)
                    #pragma unroll
                    for (int h = 0; h < 2; h++) {
                        float* c = acc[mi][nb * 2 + h];
                        uint32_t b0 = bh[nb][2 * h], b1 = bh[nb][2 * h + 1];
                        mma16816(c, ah[mi], b0, b1);                       // hi*hi
                        mma16816(c, ah[mi], bl[nb][2 * h], bl[nb][2 * h + 1]); // hi*lo
                        mma16816(c, al[mi], b0, b1);                       // lo*hi
                    }
        }
        __syncthreads();
    }

    // epilogue
    int qr = lane >> 2, qc = (lane & 3) << 1;
    #pragma unroll
    for (int mi = 0; mi < 2; mi++) {
        int r0 = m0 + wm * 32 + mi * 16 + qr;
        #pragma unroll
        for (int ni = 0; ni < 4; ni++) {
            int c = n0 + wn * 32 + ni * 8 + qc;
            float* o0 = out + ((size_t)b * SEQ + r0) * DM + c;
            float* o1 = o0 + 8 * DM;
            *reinterpret_cast<float2*>(o0) = make_float2(acc[mi][ni][0], acc[mi][ni][1]);
            *reinterpret_cast<float2*>(o1) = make_float2(acc[mi][ni][2], acc[mi][ni][3]);
        }
    }
}

// ============================ launch ============================
extern "C" void kernel_launch(void* const* d_in, const int* in_sizes, int n_in,
                              void* d_out, int out_size) {
    const float* q = (const float*)d_in[0];
    const float* k = (const float*)d_in[1];
    const float* e = (const float*)d_in[2];
    float* out = (float*)d_out;

    cudaFuncSetAttribute(rel_gemm_kernel,
                         cudaFuncAttributeMaxDynamicSharedMemorySize, SMEM_TOTAL);

    prep_q_kernel<<<BATCH * SEQ, 128>>>(q);
    prep_k_kernel<<<1024, 256>>>(k);
    prep_e_kernel<<<dim3(16, 16), dim3(32, 8)>>>(e);
    rel_gemm_kernel<<<dim3(SEQ / BN, SEQ / BM, BATCH), 256, SMEM_TOTAL>>>(out);
}

// round 6
// speedup vs baseline: 1.2374x; 1.0531x over previous
#include <cuda_runtime.h>
#include <cuda_bf16.h>
#include <cstdint>

#define BATCH 8
#define SEQ 512
#define DM 512
#define NELEM (BATCH*SEQ*DM)

// ============================ scratch (bf16 hi/lo splits) ============================
__device__ __align__(16) __nv_bfloat16 g_Qhi[NELEM];
__device__ __align__(16) __nv_bfloat16 g_Qlo[NELEM];
__device__ __align__(16) __nv_bfloat16 g_QRhi[NELEM];
__device__ __align__(16) __nv_bfloat16 g_QRlo[NELEM];
__device__ __align__(16) __nv_bfloat16 g_Khi[NELEM];
__device__ __align__(16) __nv_bfloat16 g_Klo[NELEM];
__device__ __align__(16) __nv_bfloat16 g_Ethi[DM*DM];
__device__ __align__(16) __nv_bfloat16 g_Etlo[DM*DM];

__device__ __forceinline__ void split_bf16(float x, __nv_bfloat16& h, __nv_bfloat16& l) {
    h = __float2bfloat16(x);
    l = __float2bfloat16(x - __bfloat162float(h));
}

__device__ __forceinline__ uint32_t smem_u32(const void* p) {
    uint32_t a;
    asm("{ .reg .u64 t; cvta.to.shared.u64 t, %1; cvt.u32.u64 %0, t; }" : "=r"(a) : "l"(p));
    return a;
}

// ============================ fused prep kernel ============================
// blocks [0, 4096): Q rows (split + reversal); [4096, 6144): K split; [6144, 6400): E transpose-split
#define QBLOCKS (BATCH*SEQ)
#define KBLOCKS 2048
#define EBLOCKS 256

__global__ void prep_all_kernel(const float* __restrict__ q,
                                const float* __restrict__ k,
                                const float* __restrict__ e) {
    __shared__ float sh[32 * 33 + 128];   // reused: Q row(512)+red(128) | E tile(1056)
    int bid = blockIdx.x;
    int t = threadIdx.x;                  // 128 threads

    if (bid < QBLOCKS) {
        float* row = sh;                  // 512
        float* red = sh + 512;            // 128
        int i = bid & (SEQ - 1);
        const float4* src = reinterpret_cast<const float4*>(q + (size_t)bid * DM);
        reinterpret_cast<float4*>(row)[t] = src[t];
        __syncthreads();

        float p = 0.f;
        #pragma unroll
        for (int j = t; j < DM; j += 128)
            if (j >= i) p += row[j];
        red[t] = p;
        __syncthreads();
        #pragma unroll
        for (int s = 64; s > 0; s >>= 1) {
            if (t < s) red[t] += red[t + s];
            __syncthreads();
        }
        float suf = red[0];

        size_t base = (size_t)bid * DM;
        #pragma unroll
        for (int d = t; d < DM; d += 128) {
            float x = row[d];
            split_bf16(x, g_Qhi[base + d], g_Qlo[base + d]);
            float r = (d == 0) ? suf : ((d <= i) ? row[i - d] : 0.f);
            split_bf16(r, g_QRhi[base + d], g_QRlo[base + d]);
        }
    } else if (bid < QBLOCKS + KBLOCKS) {
        int idx = (bid - QBLOCKS) * 128 + t;
        int n4 = NELEM / 4;
        int stride = KBLOCKS * 128;
        for (int j = idx; j < n4; j += stride) {
            float4 v = reinterpret_cast<const float4*>(k)[j];
            __nv_bfloat16 h[4], l[4];
            split_bf16(v.x, h[0], l[0]);
            split_bf16(v.y, h[1], l[1]);
            split_bf16(v.z, h[2], l[2]);
            split_bf16(v.w, h[3], l[3]);
            reinterpret_cast<uint2*>(g_Khi)[j] = *reinterpret_cast<uint2*>(h);
            reinterpret_cast<uint2*>(g_Klo)[j] = *reinterpret_cast<uint2*>(l);
        }
    } else {
        float (*tile)[33] = reinterpret_cast<float(*)[33]>(sh);
        int eb = bid - QBLOCKS - KBLOCKS;
        int bx = eb & 15, by = eb >> 4;
        int tx = t & 31, j0 = t >> 5;     // 4 row-groups
        #pragma unroll
        for (int j = j0; j < 32; j += 4)
            tile[j][tx] = e[(size_t)(by * 32 + j) * DM + bx * 32 + tx];
        __syncthreads();
        #pragma unroll
        for (int j = j0; j < 32; j += 4) {
            size_t o = (size_t)(bx * 32 + j) * DM + by * 32 + tx;
            split_bf16(tile[tx][j], g_Ethi[o], g_Etlo[o]);
        }
    }
}

// ============================ main GEMM (mma.sync bf16, term-shared) ============================
// out[b,i,n] = Qhi.Khi + Qhi.Klo + Qlo.Khi  +  QRhi.Ethi + QRhi.Etlo + QRlo.Ethi
// Stage holds {Ahi, Alo, Bhi, Blo} for one 64-wide K chunk; 3 terms issued term-major
// so consecutive MMAs hit different accumulators (no RAW chains).

#define BM 128
#define BN 64
#define BK 64
#define AT_B (BM * BK * 2)                  // 16384 per A tile
#define BT_B (BN * BK * 2)                  // 8192 per B tile
#define STAGE_B (2 * AT_B + 2 * BT_B)       // 49152
#define SMEM_TOTAL (2 * STAGE_B)            // 98304 (2 stages), 2 CTAs/SM
#define NCHUNK 16                           // 2 passes * 8 chunks of K=64

#define OFF_AH 0
#define OFF_AL AT_B
#define OFF_BH (2 * AT_B)
#define OFF_BL (2 * AT_B + BT_B)

__device__ __forceinline__ uint32_t sw_off(int row, int kk) {
    return (uint32_t)(row * 128 + (((kk >> 3) ^ (row & 7)) << 4) + ((kk & 7) << 1));
}

__device__ __forceinline__ void cp_async16(uint32_t saddr, const void* gaddr) {
    asm volatile("cp.async.cg.shared.global [%0], [%1], 16;" :: "r"(saddr), "l"(gaddr));
}

__device__ __forceinline__ void ldmatrix_x4(uint32_t& r0, uint32_t& r1, uint32_t& r2,
                                            uint32_t& r3, uint32_t addr) {
    asm volatile("ldmatrix.sync.aligned.m8n8.x4.shared.b16 {%0,%1,%2,%3}, [%4];"
                 : "=r"(r0), "=r"(r1), "=r"(r2), "=r"(r3) : "r"(addr));
}

__device__ __forceinline__ void mma16816(float* c, const uint32_t* a, uint32_t b0, uint32_t b1) {
    asm volatile(
        "mma.sync.aligned.m16n8k16.row.col.f32.bf16.bf16.f32 "
        "{%0,%1,%2,%3}, {%4,%5,%6,%7}, {%8,%9}, {%0,%1,%2,%3};"
        : "+f"(c[0]), "+f"(c[1]), "+f"(c[2]), "+f"(c[3])
        : "r"(a[0]), "r"(a[1]), "r"(a[2]), "r"(a[3]), "r"(b0), "r"(b1));
}

__global__ __launch_bounds__(256, 2) void rel_gemm_kernel(float* __restrict__ out) {
    extern __shared__ char smem[];
    uint32_t sb = smem_u32(smem);

    int tid = threadIdx.x;
    int lane = tid & 31, wid = tid >> 5;
    int wm = wid & 3, wn = wid >> 2;          // 4 m-warps x 2 n-warps, warp tile 32x32
    int n0 = blockIdx.x * BN;
    int m0 = blockIdx.y * BM;
    int b  = blockIdx.z;
    size_t boff = (size_t)b * SEQ * DM;

    const __nv_bfloat16* AH[2] = { g_Qhi + boff, g_QRhi + boff };
    const __nv_bfloat16* AL[2] = { g_Qlo + boff, g_QRlo + boff };
    const __nv_bfloat16* BH[2] = { g_Khi + boff, g_Ethi };
    const __nv_bfloat16* BL[2] = { g_Klo + boff, g_Etlo };

    float acc[2][4][4];
    #pragma unroll
    for (int mi = 0; mi < 2; mi++)
        #pragma unroll
        for (int ni = 0; ni < 4; ni++)
            #pragma unroll
            for (int j = 0; j < 4; j++) acc[mi][ni][j] = 0.f;

    auto load_chunk = [&](int it, int buf) {
        int pass = it >> 3, kc = it & 7;
        const __nv_bfloat16* ah = AH[pass] + (size_t)m0 * DM + kc * BK;
        const __nv_bfloat16* al = AL[pass] + (size_t)m0 * DM + kc * BK;
        const __nv_bfloat16* bh = BH[pass] + (size_t)n0 * DM + kc * BK;
        const __nv_bfloat16* bl = BL[pass] + (size_t)n0 * DM + kc * BK;
        uint32_t st = sb + buf * STAGE_B;
        #pragma unroll
        for (int r2 = 0; r2 < 4; r2++) {          // A tiles: 128 rows x 8 chunks
            int idx = tid + r2 * 256;
            int row = idx >> 3, ck = idx & 7;
            uint32_t so = (uint32_t)(row * 128 + ((ck ^ (row & 7)) << 4));
            cp_async16(st + OFF_AH + so, ah + row * DM + ck * 8);
            cp_async16(st + OFF_AL + so, al + row * DM + ck * 8);
        }
        #pragma unroll
        for (int r2 = 0; r2 < 2; r2++) {          // B tiles: 64 rows x 8 chunks
            int idx = tid + r2 * 256;
            int row = idx >> 3, ck = idx & 7;
            uint32_t so = (uint32_t)(row * 128 + ((ck ^ (row & 7)) << 4));
            cp_async16(st + OFF_BH + so, bh + row * DM + ck * 8);
            cp_async16(st + OFF_BL + so, bl + row * DM + ck * 8);
        }
        asm volatile("cp.async.commit_group;");
    };

    load_chunk(0, 0);

    for (int it = 0; it < NCHUNK; it++) {
        if (it + 1 < NCHUNK) {
            load_chunk(it + 1, (it + 1) & 1);
            asm volatile("cp.async.wait_group 1;");
        } else {
            asm volatile("cp.async.wait_group 0;");
        }
        __syncthreads();

        uint32_t st = sb + (it & 1) * STAGE_B;

        #pragma unroll
        for (int k16 = 0; k16 < 4; k16++) {
            int kc = k16 * 16;
            uint32_t ah[2][4], al[2][4];
            #pragma unroll
            for (int mi = 0; mi < 2; mi++) {
                int row = wm * 32 + mi * 16 + (lane & 7) + ((lane >> 3) & 1) * 8;
                int kk  = kc + ((lane >> 4) << 3);
                uint32_t so = sw_off(row, kk);
                ldmatrix_x4(ah[mi][0], ah[mi][1], ah[mi][2], ah[mi][3], st + OFF_AH + so);
                ldmatrix_x4(al[mi][0], al[mi][1], al[mi][2], al[mi][3], st + OFF_AL + so);
            }
            uint32_t bh[2][4], bl[2][4];
            #pragma unroll
            for (int nb = 0; nb < 2; nb++) {
                int row = wn * 32 + nb * 16 + (lane & 7) + ((lane >> 4) << 3);
                int kk  = kc + (((lane >> 3) & 1) << 3);
                uint32_t so = sw_off(row, kk);
                ldmatrix_x4(bh[nb][0], bh[nb][1], bh[nb][2], bh[nb][3], st + OFF_BH + so);
                ldmatrix_x4(bl[nb][0], bl[nb][1], bl[nb][2], bl[nb][3], st + OFF_BL + so);
            }
            // term-major: 3 groups of 8 independent MMAs (no back-to-back RAW)
            #pragma unroll
            for (int mi = 0; mi < 2; mi++)            // hi*hi
                #pragma unroll
                for (int nb = 0; nb < 2; nb++)
                    #pragma unroll
                    for (int h = 0; h < 2; h++)
                        mma16816(acc[mi][nb * 2 + h], ah[mi], bh[nb][2 * h], bh[nb][2 * h + 1]);
            #pragma unroll
            for (int mi = 0; mi < 2; mi++)            // hi*lo
                #pragma unroll
                for (int nb = 0; nb < 2; nb++)
                    #pragma unroll
                    for (int h = 0; h < 2; h++)
                        mma16816(acc[mi][nb * 2 + h], ah[mi], bl[nb][2 * h], bl[nb][2 * h + 1]);
            #pragma unroll
            for (int mi = 0; mi < 2; mi++)            // lo*hi
                #pragma unroll
                for (int nb = 0; nb < 2; nb++)
                    #pragma unroll
                    for (int h = 0; h < 2; h++)
                        mma16816(acc[mi][nb * 2 + h], al[mi], bh[nb][2 * h], bh[nb][2 * h + 1]);
        }
        __syncthreads();
    }

    // epilogue
    int qr = lane >> 2, qc = (lane & 3) << 1;
    #pragma unroll
    for (int mi = 0; mi < 2; mi++) {
        int r0 = m0 + wm * 32 + mi * 16 + qr;
        #pragma unroll
        for (int ni = 0; ni < 4; ni++) {
            int c = n0 + wn * 32 + ni * 8 + qc;
            float* o0 = out + ((size_t)b * SEQ + r0) * DM + c;
            float* o1 = o0 + 8 * DM;
            *reinterpret_cast<float2*>(o0) = make_float2(acc[mi][ni][0], acc[mi][ni][1]);
            *reinterpret_cast<float2*>(o1) = make_float2(acc[mi][ni][2], acc[mi][ni][3]);
        }
    }
}

// ============================ launch ============================
extern "C" void kernel_launch(void* const* d_in, const int* in_sizes, int n_in,
                              void* d_out, int out_size) {
    const float* q = (const float*)d_in[0];
    const float* k = (const float*)d_in[1];
    const float* e = (const float*)d_in[2];
    float* out = (float*)d_out;

    cudaFuncSetAttribute(rel_gemm_kernel,
                         cudaFuncAttributeMaxDynamicSharedMemorySize, SMEM_TOTAL);

    prep_all_kernel<<<QBLOCKS + KBLOCKS + EBLOCKS, 128>>>(q, k, e);
    rel_gemm_kernel<<<dim3(SEQ / BN, SEQ / BM, BATCH), 256, SMEM_TOTAL>>>(out);
}